// round 11
// baseline (speedup 1.0000x reference)
#include <cuda_runtime.h>
#include <cuda_bf16.h>

// Problem constants: B=16, N=256, D=64.
#define Bn 16
#define Nn 256
#define Dn 64
#define G  4      // rows per value block
#define JS 4      // j-range splits -> 64 j's per value block

__device__ float g_s[Bn * Nn];   // s[b,j] (ba/2 folded in)
__device__ float g_m[Bn * Nn];   // row max of leaky(s_i+s_j)
__device__ float g_r[Bn * Nn];   // 1 / row sum of exp(x - m)

// ---------------- stats kernel: grid = Bn*4 = 64 blocks, 256 threads -----------
__global__ __launch_bounds__(256) void stats_kernel(
        const float* __restrict__ emb,
        const float* __restrict__ W,
        const float* __restrict__ bW,
        const float* __restrict__ a,
        const float* __restrict__ ba) {
    const int tid = threadIdx.x;
    const int b = blockIdx.x >> 2;
    const int q = blockIdx.x & 3;

    __shared__ float pv[4][Dn];   // partial v
    __shared__ float sv[Dn];
    __shared__ float sc;
    __shared__ float ss[Nn];
    __shared__ float red[8];

    // v = W^T a : 4 threads per output d, 16 MACs each (short chains, coalesced W)
    {
        const int d  = tid & 63;
        const int e0 = (tid >> 6) * 16;
        float acc = 0.f;
#pragma unroll
        for (int e = 0; e < 16; e++) acc = fmaf(a[e0 + e], W[(e0 + e) * Dn + d], acc);
        pv[tid >> 6][d] = acc;
    }
    __syncthreads();
    if (tid < 64) {
        sv[tid] = pv[0][tid] + pv[1][tid] + pv[2][tid] + pv[3][tid];
    } else if (tid < 96) {
        int l = tid - 64;
        float acc = a[l] * bW[l] + a[l + 32] * bW[l + 32];
#pragma unroll
        for (int o = 16; o; o >>= 1) acc += __shfl_xor_sync(0xFFFFFFFFu, acc, o);
        if (l == 0) sc = acc + 0.5f * ba[0];
    }
    __syncthreads();

    // s_j, one per thread
    {
        const float4* myrow = (const float4*)(emb + ((size_t)b * Nn + tid) * Dn);
        const float4* v4 = (const float4*)sv;
        float acc = 0.f;
#pragma unroll
        for (int k = 0; k < Dn / 4; k++) {
            float4 e = myrow[k], v = v4[k];
            acc += e.x * v.x + e.y * v.y + e.z * v.z + e.w * v.w;
        }
        acc += sc;
        ss[tid] = acc;
        g_s[b * Nn + tid] = acc;
    }
    __syncthreads();

    // block max of s
    float mx = ss[tid];
#pragma unroll
    for (int o = 16; o; o >>= 1) mx = fmaxf(mx, __shfl_xor_sync(0xFFFFFFFFu, mx, o));
    if ((tid & 31) == 0) red[tid >> 5] = mx;
    __syncthreads();
    float smax = red[0];
#pragma unroll
    for (int w = 1; w < 8; w++) smax = fmaxf(smax, red[w]);

    // rows of this quarter: 4 threads per row, each sums 64 j's
    const int i  = q * 64 + (tid >> 2);
    const int j0 = (tid & 3) * 64;
    const float s_i = ss[i];
    float t = s_i + smax;
    const float m_i = (t >= 0.f) ? t : 0.01f * t;   // leaky monotone -> true row max

    float sum = 0.f;
#pragma unroll 8
    for (int j = 0; j < 64; j++) {
        float x = s_i + ss[j0 + j];
        x = (x >= 0.f) ? x : 0.01f * x;
        sum += __expf(x - m_i);
    }
    sum += __shfl_xor_sync(0xFFFFFFFFu, sum, 1);
    sum += __shfl_xor_sync(0xFFFFFFFFu, sum, 2);
    if ((tid & 3) == 0) {
        g_m[b * Nn + i] = m_i;
        g_r[b * Nn + i] = 1.0f / sum;
    }
}

// ---------------- alpha kernel: grid = Bn*64 = 1024, 256 threads ---------------
__global__ __launch_bounds__(256) void alpha_kernel(
        float* __restrict__ out_alpha) {
    const int tid = threadIdx.x;
    const int rg = blockIdx.x & 63;
    const int b  = blockIdx.x >> 6;
    const int i0 = rg * G;

    __shared__ float ss[Nn];
    ss[tid] = g_s[b * Nn + tid];
    __syncthreads();

    const float s_j = ss[tid];
#pragma unroll
    for (int g = 0; g < G; g++) {
        const int i = i0 + g;
        const float s_i = ss[i];
        float x = s_i + s_j;
        x = (x >= 0.f) ? x : 0.01f * x;
        const float al = __expf(x - g_m[b * Nn + i]) * g_r[b * Nn + i];
        out_alpha[((size_t)(b * Nn + i)) * Nn + tid] = al;
    }
}

// ---------------- value kernel: grid = 4096, 256 threads -----------------------
// block (b, rg, jq): value[b, i0..i0+3, j0..j0+63, :] = ei (x) ej.
// No smem, no syncthreads: eir loaded directly (L2-hot, once per block).
// Store addresses = one base + compile-time 64KB immediate offsets per g.
// Target: <=36 regs so launch_bounds(256,7) holds WITHOUT spill ->
// 1036 resident blocks, 4096/1036 = 3.95 waves (near-perfect packing).
__global__ __launch_bounds__(256, 7) void value_kernel(
        const float* __restrict__ emb,
        float* __restrict__ out_value) { // [B,N,N,D]
    const int tid = threadIdx.x;
    const int jq = blockIdx.x & (JS - 1);
    const int rg = (blockIdx.x >> 2) & 63;
    const int b  = blockIdx.x >> 8;
    const int i0 = rg * G;
    const int j0 = jq * 64;

    const float4* embB4 = (const float4*)(emb + (size_t)b * Nn * Dn);

    // eir[g] = emb[b, i0+g, 4*(tid&15) .. +3]
    const int d4 = tid & 15;
    float4 eir[G];
#pragma unroll
    for (int g = 0; g < G; g++)
        eir[g] = __ldg(&embB4[(i0 + g) * (Dn / 4) + d4]);

    const float4* ejb = embB4 + j0 * (Dn / 4);
    float4* ovb = (float4*)out_value + ((size_t)(b * Nn + i0) * Nn + j0) * (Dn / 4);
#pragma unroll
    for (int k = 0; k < 4; k++) {
        const int idx = k * 256 + tid;        // jloc = idx>>4, d4 = idx&15
        const float4 ej = ejb[idx];
#pragma unroll
        for (int g = 0; g < G; g++) {
            float4 r;
            r.x = eir[g].x * ej.x;
            r.y = eir[g].y * ej.y;
            r.z = eir[g].z * ej.z;
            r.w = eir[g].w * ej.w;
            // g * Nn * (Dn/4) = g * 4096 float4 -> immediate offset in STG
            __stcs(ovb + g * (Nn * Dn / 4) + idx, r);
        }
    }
}

// ---------------- forked-capture plumbing --------------------------------------
static cudaStream_t g_s1;
static cudaEvent_t  g_e0, g_e1;
static bool g_forked = false;
namespace {
struct _Init {
    _Init() {
        g_forked =
            cudaStreamCreateWithFlags(&g_s1, cudaStreamNonBlocking) == cudaSuccess &&
            cudaEventCreateWithFlags(&g_e0, cudaEventDisableTiming) == cudaSuccess &&
            cudaEventCreateWithFlags(&g_e1, cudaEventDisableTiming) == cudaSuccess;
    }
};
_Init _init_once;
}

extern "C" void kernel_launch(void* const* d_in, const int* in_sizes, int n_in,
                              void* d_out, int out_size) {
    const float* emb = (const float*)d_in[0];
    const float* W   = (const float*)d_in[1];
    const float* bW  = (const float*)d_in[2];
    const float* a   = (const float*)d_in[3];
    const float* ba  = (const float*)d_in[4];

    float* out_alpha = (float*)d_out;                        // B*N*N floats
    float* out_value = (float*)d_out + (size_t)Bn * Nn * Nn; // B*N*N*D floats

    if (g_forked) {
        // side stream: stats -> alpha, concurrent with the big value stream
        cudaEventRecord(g_e0, 0);
        cudaStreamWaitEvent(g_s1, g_e0, 0);
        stats_kernel<<<Bn * 4, 256, 0, g_s1>>>(emb, W, bW, a, ba);
        alpha_kernel<<<Bn * (Nn / G), 256, 0, g_s1>>>(out_alpha);
        cudaEventRecord(g_e1, g_s1);
        value_kernel<<<Bn * (Nn / G) * JS, 256>>>(emb, out_value);
        cudaStreamWaitEvent(0, g_e1, 0);
    } else {
        stats_kernel<<<Bn * 4, 256>>>(emb, W, bW, a, ba);
        alpha_kernel<<<Bn * (Nn / G), 256>>>(out_alpha);
        value_kernel<<<Bn * (Nn / G) * JS, 256>>>(emb, out_value);
    }
}

// round 12
// speedup vs baseline: 1.0460x; 1.0460x over previous
#include <cuda_runtime.h>
#include <cuda_bf16.h>

// Problem constants: B=16, N=256, D=64.
#define Bn 16
#define Nn 256
#define Dn 64
#define G  2      // rows per value block (small -> tiny reg footprint)
#define JS 4      // j-range splits -> 64 j's per value block

__device__ float g_s[Bn * Nn];   // s[b,j] (ba/2 folded in)
__device__ float g_m[Bn * Nn];   // row max of leaky(s_i+s_j)
__device__ float g_r[Bn * Nn];   // 1 / row sum of exp(x - m)

// ---------------- stats kernel: grid = Bn*4 = 64 blocks, 256 threads -----------
__global__ __launch_bounds__(256) void stats_kernel(
        const float* __restrict__ emb,
        const float* __restrict__ W,
        const float* __restrict__ bW,
        const float* __restrict__ a,
        const float* __restrict__ ba) {
    const int tid = threadIdx.x;
    const int b = blockIdx.x >> 2;
    const int q = blockIdx.x & 3;

    __shared__ float pv[4][Dn];   // partial v
    __shared__ float sv[Dn];
    __shared__ float sc;
    __shared__ float ss[Nn];
    __shared__ float red[8];

    // v = W^T a : 4 threads per output d, 16 MACs each (short chains, coalesced W)
    {
        const int d  = tid & 63;
        const int e0 = (tid >> 6) * 16;
        float acc = 0.f;
#pragma unroll
        for (int e = 0; e < 16; e++) acc = fmaf(a[e0 + e], W[(e0 + e) * Dn + d], acc);
        pv[tid >> 6][d] = acc;
    }
    __syncthreads();
    if (tid < 64) {
        sv[tid] = pv[0][tid] + pv[1][tid] + pv[2][tid] + pv[3][tid];
    } else if (tid < 96) {
        int l = tid - 64;
        float acc = a[l] * bW[l] + a[l + 32] * bW[l + 32];
#pragma unroll
        for (int o = 16; o; o >>= 1) acc += __shfl_xor_sync(0xFFFFFFFFu, acc, o);
        if (l == 0) sc = acc + 0.5f * ba[0];
    }
    __syncthreads();

    // s_j, one per thread
    {
        const float4* myrow = (const float4*)(emb + ((size_t)b * Nn + tid) * Dn);
        const float4* v4 = (const float4*)sv;
        float acc = 0.f;
#pragma unroll
        for (int k = 0; k < Dn / 4; k++) {
            float4 e = myrow[k], v = v4[k];
            acc += e.x * v.x + e.y * v.y + e.z * v.z + e.w * v.w;
        }
        acc += sc;
        ss[tid] = acc;
        g_s[b * Nn + tid] = acc;
    }
    __syncthreads();

    // block max of s
    float mx = ss[tid];
#pragma unroll
    for (int o = 16; o; o >>= 1) mx = fmaxf(mx, __shfl_xor_sync(0xFFFFFFFFu, mx, o));
    if ((tid & 31) == 0) red[tid >> 5] = mx;
    __syncthreads();
    float smax = red[0];
#pragma unroll
    for (int w = 1; w < 8; w++) smax = fmaxf(smax, red[w]);

    // rows of this quarter: 4 threads per row, each sums 64 j's
    const int i  = q * 64 + (tid >> 2);
    const int j0 = (tid & 3) * 64;
    const float s_i = ss[i];
    float t = s_i + smax;
    const float m_i = (t >= 0.f) ? t : 0.01f * t;   // leaky monotone -> true row max

    float sum = 0.f;
#pragma unroll 8
    for (int j = 0; j < 64; j++) {
        float x = s_i + ss[j0 + j];
        x = (x >= 0.f) ? x : 0.01f * x;
        sum += __expf(x - m_i);
    }
    sum += __shfl_xor_sync(0xFFFFFFFFu, sum, 1);
    sum += __shfl_xor_sync(0xFFFFFFFFu, sum, 2);
    if ((tid & 3) == 0) {
        g_m[b * Nn + i] = m_i;
        g_r[b * Nn + i] = 1.0f / sum;
    }
}

// ---------------- alpha kernel: grid = Bn*64 = 1024, 256 threads ---------------
__global__ __launch_bounds__(256) void alpha_kernel(
        float* __restrict__ out_alpha) {
    const int tid = threadIdx.x;
    const int rg = blockIdx.x & 63;
    const int b  = blockIdx.x >> 6;
    const int i0 = rg * 4;

    __shared__ float ss[Nn];
    ss[tid] = g_s[b * Nn + tid];
    __syncthreads();

    const float s_j = ss[tid];
#pragma unroll
    for (int g = 0; g < 4; g++) {
        const int i = i0 + g;
        const float s_i = ss[i];
        float x = s_i + s_j;
        x = (x >= 0.f) ? x : 0.01f * x;
        const float al = __expf(x - g_m[b * Nn + i]) * g_r[b * Nn + i];
        out_alpha[((size_t)(b * Nn + i)) * Nn + tid] = al;
    }
}

// ---------------- value kernel: grid = 8192, 256 threads -----------------------
// block (b, rg, jq): value[b, i0..i0+1, j0..j0+63, :] = ei (x) ej.
// G=2: live set ~26-30 regs -> launch_bounds(256,8) (32-reg budget) without
// spill. 8 blocks/SM -> 1184 resident -> 8192/1184 = 6.92 waves (~1% tail).
__global__ __launch_bounds__(256, 8) void value_kernel(
        const float* __restrict__ emb,
        float* __restrict__ out_value) { // [B,N,N,D]
    const int tid = threadIdx.x;
    const int jq = blockIdx.x & (JS - 1);
    const int rg = (blockIdx.x >> 2) & 127;
    const int b  = blockIdx.x >> 9;
    const int i0 = rg * G;
    const int j0 = jq * 64;

    const float4* embB4 = (const float4*)(emb + (size_t)b * Nn * Dn);

    // eir[g] = emb[b, i0+g, 4*(tid&15) .. +3]  (L2-hot, once per block)
    const int d4 = tid & 15;
    float4 eir[G];
#pragma unroll
    for (int g = 0; g < G; g++)
        eir[g] = __ldg(&embB4[(i0 + g) * (Dn / 4) + d4]);

    const float4* ejb = embB4 + j0 * (Dn / 4);
    float4* ovb = (float4*)out_value + ((size_t)(b * Nn + i0) * Nn + j0) * (Dn / 4);
#pragma unroll
    for (int k = 0; k < 4; k++) {
        const int idx = k * 256 + tid;        // jloc = idx>>4, d4 = idx&15
        const float4 ej = ejb[idx];
#pragma unroll
        for (int g = 0; g < G; g++) {
            float4 r;
            r.x = eir[g].x * ej.x;
            r.y = eir[g].y * ej.y;
            r.z = eir[g].z * ej.z;
            r.w = eir[g].w * ej.w;
            // g * Nn * (Dn/4) = g * 4096 float4 -> immediate offset in STG
            __stcs(ovb + g * (Nn * Dn / 4) + idx, r);
        }
    }
}

// ---------------- forked-capture plumbing --------------------------------------
static cudaStream_t g_s1;
static cudaEvent_t  g_e0, g_e1;
static bool g_forked = false;
namespace {
struct _Init {
    _Init() {
        g_forked =
            cudaStreamCreateWithFlags(&g_s1, cudaStreamNonBlocking) == cudaSuccess &&
            cudaEventCreateWithFlags(&g_e0, cudaEventDisableTiming) == cudaSuccess &&
            cudaEventCreateWithFlags(&g_e1, cudaEventDisableTiming) == cudaSuccess;
    }
};
_Init _init_once;
}

extern "C" void kernel_launch(void* const* d_in, const int* in_sizes, int n_in,
                              void* d_out, int out_size) {
    const float* emb = (const float*)d_in[0];
    const float* W   = (const float*)d_in[1];
    const float* bW  = (const float*)d_in[2];
    const float* a   = (const float*)d_in[3];
    const float* ba  = (const float*)d_in[4];

    float* out_alpha = (float*)d_out;                        // B*N*N floats
    float* out_value = (float*)d_out + (size_t)Bn * Nn * Nn; // B*N*N*D floats

    if (g_forked) {
        // side stream: stats -> alpha, concurrent with the big value stream
        cudaEventRecord(g_e0, 0);
        cudaStreamWaitEvent(g_s1, g_e0, 0);
        stats_kernel<<<Bn * 4, 256, 0, g_s1>>>(emb, W, bW, a, ba);
        alpha_kernel<<<Bn * 64, 256, 0, g_s1>>>(out_alpha);
        cudaEventRecord(g_e1, g_s1);
        value_kernel<<<Bn * (Nn / G) * JS, 256>>>(emb, out_value);
        cudaStreamWaitEvent(0, g_e1, 0);
    } else {
        stats_kernel<<<Bn * 4, 256>>>(emb, W, bW, a, ba);
        alpha_kernel<<<Bn * 64, 256>>>(out_alpha);
        value_kernel<<<Bn * (Nn / G) * JS, 256>>>(emb, out_value);
    }
}